// round 15
// baseline (speedup 1.0000x reference)
#include <cuda_runtime.h>
#include <cuda_fp16.h>
#include <math.h>
#include <stdint.h>

// Problem dims
constexpr int BATCH = 2;
constexpr int SEQ   = 2048;
constexpr int HID   = 4096;
constexpr int NHEADS = 32;
constexpr int NKVH   = 8;
constexpr int HDIM   = 128;
constexpr int GRP    = NHEADS / NKVH;          // 4
constexpr int MROWS  = BATCH * SEQ;            // 4096
constexpr int NQCOLS = NHEADS * HDIM;          // 4096
constexpr int NKVCOLS = NKVH * HDIM;           // 1024
constexpr int NQKV   = NQCOLS + 2 * NKVCOLS;   // 6144

// Scratch (device globals; no runtime allocation allowed)
__device__ float  g_Q [(size_t)MROWS * NQCOLS];
__device__ float  g_K [(size_t)MROWS * NKVCOLS];
__device__ float  g_V [(size_t)MROWS * NKVCOLS];
__device__ __half g_AOh[(size_t)MROWS * NQCOLS];
__device__ __half g_Xh [(size_t)MROWS * HID];
__device__ __half g_Wqkvh[(size_t)NQKV * HID];      // [Wq; Wk; Wv] rows
__device__ __half g_Woh[(size_t)HID * NQCOLS];

// ---------------------------------------------------------------------------
// helpers
// ---------------------------------------------------------------------------
__device__ __forceinline__ void mma_f16(float c[4], const uint32_t a[4], const uint32_t b[2]) {
    asm volatile(
        "mma.sync.aligned.m16n8k16.row.col.f32.f16.f16.f32 "
        "{%0,%1,%2,%3}, {%4,%5,%6,%7}, {%8,%9}, {%0,%1,%2,%3};\n"
        : "+f"(c[0]), "+f"(c[1]), "+f"(c[2]), "+f"(c[3])
        : "r"(a[0]), "r"(a[1]), "r"(a[2]), "r"(a[3]), "r"(b[0]), "r"(b[1]));
}

__device__ __forceinline__ void split_pair(float x0, float x1, uint32_t& hi, uint32_t& lo) {
    __half2 h = __float22half2_rn(make_float2(x0, x1));
    float l0 = x0 - __low2float(h);
    float l1 = x1 - __high2float(h);
    __half2 l = __float22half2_rn(make_float2(l0, l1));
    hi = *reinterpret_cast<uint32_t*>(&h);
    lo = *reinterpret_cast<uint32_t*>(&l);
}

__device__ __forceinline__ uint32_t round_pair(float x0, float x1) {
    __half2 h = __float22half2_rn(make_float2(x0, x1));
    return *reinterpret_cast<uint32_t*>(&h);
}

__device__ __forceinline__ uint32_t smem_u32(const void* p) {
    uint32_t a;
    asm("{ .reg .u64 t; cvta.to.shared.u64 t, %1; cvt.u32.u64 %0, t; }" : "=r"(a) : "l"(p));
    return a;
}

#define LDSM4(r0, r1, r2, r3, a) \
    asm volatile("ldmatrix.sync.aligned.m8n8.x4.shared.b16 {%0,%1,%2,%3}, [%4];" \
                 : "=r"(r0), "=r"(r1), "=r"(r2), "=r"(r3) : "r"(a))

#define CP_ASYNC16(sa, gp) \
    asm volatile("cp.async.cg.shared.global [%0], [%1], 16;" :: "r"(sa), "l"(gp))
#define CP_COMMIT() asm volatile("cp.async.commit_group;" ::: "memory")
#define CP_WAIT(n)  asm volatile("cp.async.wait_group %0;" :: "n"(n) : "memory")

// ---------------------------------------------------------------------------
// pre-convert kernel (round fp32 -> fp16)
// ---------------------------------------------------------------------------
__global__ void cvt_round_kernel(const float* __restrict__ X, __half* __restrict__ Xh, int n)
{
    const int i = (blockIdx.x * 256 + threadIdx.x) * 4;
    if (i >= n) return;
    float4 v = *reinterpret_cast<const float4*>(X + i);
    *reinterpret_cast<uint2*>(Xh + i) =
        make_uint2(round_pair(v.x, v.y), round_pair(v.z, v.w));
}

// ---------------------------------------------------------------------------
// fp16 1-term GEMM NT, cp.async 2-stage pipeline, 3-way output routing.
// (R14-proven.)
// ---------------------------------------------------------------------------
constexpr int TBM = 128, TBN = 128, TBK = 32;
constexpr int GST = 40;
constexpr int TILE_HB  = TBM * GST;
constexpr int STAGE_B  = 2 * TILE_HB * 2;       // 20480
constexpr int GEMM_SMEM = 2 * STAGE_B;          // 40960

__global__ __launch_bounds__(256, 2)
void hgemm_nt_1t(const __half* __restrict__ A, const __half* __restrict__ Bh_g,
                 float* __restrict__ Cq, float* __restrict__ Ck, float* __restrict__ Cv,
                 int Kdim)
{
    extern __shared__ __half sm[];
    __half* Ahs = sm;
    __half* Bhs = sm + TILE_HB;

    const int tid  = threadIdx.x;
    const int lane = tid & 31;
    const int wid  = tid >> 5;
    const int wm   = (wid >> 1) * 32;
    const int wn   = (wid & 1) * 64;
    const int lr   = lane >> 2;
    const int lc   = lane & 3;
    const int bm0  = blockIdx.y * TBM;
    const int bn0  = blockIdx.x * TBN;

    const int crow = tid >> 2;
    const int ccol = (tid & 3) * 8;

    const __half* Ap  = A    + (size_t)(bm0 + crow) * Kdim + ccol;
    const __half* Bhp = Bh_g + (size_t)(bn0 + crow) * Kdim + ccol;
    const size_t rstep = (size_t)64 * Kdim;

    uint32_t aFill  = smem_u32(&Ahs[crow * GST + ccol]);
    uint32_t bhFill = smem_u32(&Bhs[crow * GST + ccol]);
    const uint32_t rowB = 64 * GST * 2;

    const int lrow = lane & 7;
    const int lblk = lane >> 3;
    const int rofs = (lblk & 1) * 8 + lrow;
    const int cofs = (lblk >> 1) * 8;
    uint32_t aAddr[2], bhAddr[4];
#pragma unroll
    for (int mt = 0; mt < 2; mt++)
        aAddr[mt] = smem_u32(&Ahs[(wm + mt * 16 + rofs) * GST + cofs]);
#pragma unroll
    for (int p = 0; p < 4; p++)
        bhAddr[p] = smem_u32(&Bhs[(wn + p * 16 + rofs) * GST + cofs]);

    auto fill = [&](int stage, int k0) {
        const uint32_t so = stage * (uint32_t)STAGE_B;
#pragma unroll
        for (int p = 0; p < 2; p++) {
            CP_ASYNC16(aFill  + so + p * rowB, Ap  + k0 + p * rstep);
            CP_ASYNC16(bhFill + so + p * rowB, Bhp + k0 + p * rstep);
        }
    };

    float cfr[2][8][4];
#pragma unroll
    for (int mt = 0; mt < 2; mt++)
#pragma unroll
        for (int nt = 0; nt < 8; nt++)
#pragma unroll
            for (int q = 0; q < 4; q++) cfr[mt][nt][q] = 0.f;

    const int nt_tiles = Kdim / TBK;

    fill(0, 0);
    CP_COMMIT();

    for (int i = 0; i < nt_tiles; i++) {
        if (i + 1 < nt_tiles) {
            fill((i + 1) & 1, (i + 1) * TBK);
            CP_COMMIT();
            CP_WAIT(1);
        } else {
            CP_WAIT(0);
        }
        __syncthreads();

        const uint32_t so = (i & 1) * (uint32_t)STAGE_B;
#pragma unroll
        for (int ks = 0; ks < 2; ks++) {
            const uint32_t kbyte = so + ks * 32;
            uint32_t ah[2][4];
            LDSM4(ah[0][0], ah[0][1], ah[0][2], ah[0][3], aAddr[0] + kbyte);
            LDSM4(ah[1][0], ah[1][1], ah[1][2], ah[1][3], aAddr[1] + kbyte);
#pragma unroll
            for (int p = 0; p < 4; p++) {
                uint32_t h0, h1, h2, h3;
                LDSM4(h0, h1, h2, h3, bhAddr[p] + kbyte);
                const uint32_t be[2] = {h0, h2}, bo[2] = {h1, h3};
                mma_f16(cfr[0][2 * p],     ah[0], be);
                mma_f16(cfr[1][2 * p],     ah[1], be);
                mma_f16(cfr[0][2 * p + 1], ah[0], bo);
                mma_f16(cfr[1][2 * p + 1], ah[1], bo);
            }
        }
        __syncthreads();
    }

    float* Cp;
    int Ndim, colbase;
    if (bn0 < NQCOLS)                 { Cp = Cq; Ndim = NQCOLS;  colbase = bn0; }
    else if (bn0 < NQCOLS + NKVCOLS)  { Cp = Ck; Ndim = NKVCOLS; colbase = bn0 - NQCOLS; }
    else                              { Cp = Cv; Ndim = NKVCOLS; colbase = bn0 - NQCOLS - NKVCOLS; }

#pragma unroll
    for (int mt = 0; mt < 2; mt++)
#pragma unroll
        for (int nt = 0; nt < 8; nt++) {
            const int row = bm0 + wm + mt * 16 + lr;
            const int col = colbase + wn + nt * 8 + lc * 2;
            *reinterpret_cast<float2*>(&Cp[(size_t)row * Ndim + col]) =
                make_float2(cfr[mt][nt][0], cfr[mt][nt][1]);
            *reinterpret_cast<float2*>(&Cp[(size_t)(row + 8) * Ndim + col]) =
                make_float2(cfr[mt][nt][2], cfr[mt][nt][3]);
        }
}

// ---------------------------------------------------------------------------
// Flash attention: scores = (Qh+Ql)·Kh (2-term), PV = Ph·Vh (1-term).
// ALL fragments via ldmatrix: Q/K row-major (GEMM A/B recipe), V stored
// TRANSPOSED in smem (Vt[d][kv], stride 72 => conflict-free LDSM).
// RoPE fused into Q/K loads. fp16 output. Heavy q-tiles first. 2 CTAs/SM.
// ---------------------------------------------------------------------------
constexpr int FBQ = 64;
constexpr int FBK = 64;
constexpr int H_ST  = 136;   // halves; 272B rows => LDSM unit stride 17 ≡ 1 mod 8
constexpr int VT_ST = 72;    // halves; 144B rows => LDSM unit stride 9  ≡ 1 mod 8
constexpr int SS_ST = 68;
constexpr int FLASH_SMEM_BYTES =
    3 * (64 * H_ST * 2) + (HDIM * VT_ST * 2) + (FBQ * SS_ST + 3 * FBQ) * 4;  // 88832

__global__ __launch_bounds__(256, 2)
void flash_kernel(const float* __restrict__ Qf, const float* __restrict__ Kf,
                  const float* __restrict__ Vf, __half* __restrict__ Oh,
                  const float* __restrict__ cosv, const float* __restrict__ sinv)
{
    extern __shared__ char smraw[];
    __half* Qh = reinterpret_cast<__half*>(smraw);   // [64][136]
    __half* Ql = Qh + 64 * H_ST;                     // [64][136]
    __half* Kh = Ql + 64 * H_ST;                     // [64][136]
    __half* Vt = Kh + 64 * H_ST;                     // [128][72] transposed V
    float*  Ss = reinterpret_cast<float*>(Vt + HDIM * VT_ST);
    float* m_sm = Ss + FBQ * SS_ST;
    float* l_sm = m_sm + FBQ;
    float* a_sm = l_sm + FBQ;

    const int tid = threadIdx.x;
    const int lane = tid & 31;
    const int wid = tid >> 5;
    const int lr = lane >> 2;
    const int lc = lane & 3;

    const int qt = gridDim.x - 1 - blockIdx.x;   // heavy tiles first
    const int bh = blockIdx.y;
    const int b = bh / NHEADS;
    const int h = bh - b * NHEADS;
    const int hk = h / GRP;

    const float SCALE = 0.0883883476483184f;

    const int wmS = (wid >> 1) * 16;
    const int wnS = (wid & 1) * 32;
    const int wmP = wmS;
    const int wnP = (wid & 1) * 64;

    // ldmatrix lane addressing (GEMM-proven recipe)
    const int lrow = lane & 7;
    const int lblk = lane >> 3;
    const int rofs = (lblk & 1) * 8 + lrow;
    const int cofs = (lblk >> 1) * 8;

    const uint32_t aQh = smem_u32(&Qh[(wmS + rofs) * H_ST + cofs]);
    const uint32_t aQl = smem_u32(&Ql[(wmS + rofs) * H_ST + cofs]);
    uint32_t bK[2], bV[4];
#pragma unroll
    for (int p = 0; p < 2; p++)
        bK[p] = smem_u32(&Kh[(wnS + p * 16 + rofs) * H_ST + cofs]);
#pragma unroll
    for (int p = 0; p < 4; p++)
        bV[p] = smem_u32(&Vt[(wnP + p * 16 + rofs) * VT_ST + cofs]);

    // ---- Q tile: fused RoPE + hi/lo split ----
    {
        const size_t qbase = ((size_t)(b * SEQ + qt * FBQ)) * NQCOLS + h * HDIM;
#pragma unroll
        for (int it = 0; it < 8; it++) {
            const int f = tid + it * 256;
            const int r = f >> 5;
            const int d = (f & 31) * 4;
            const int t = qt * FBQ + r;
            float4 v = *reinterpret_cast<const float4*>(&Qf[qbase + (size_t)r * NQCOLS + d]);
            const float c0 = cosv[t * 64 + d / 2],     s0 = sinv[t * 64 + d / 2];
            const float c1 = cosv[t * 64 + d / 2 + 1], s1 = sinv[t * 64 + d / 2 + 1];
            float x0 = v.x * c0 - v.y * s0, x1 = v.x * s0 + v.y * c0;
            float x2 = v.z * c1 - v.w * s1, x3 = v.z * s1 + v.w * c1;
            uint32_t h0, l0, h1, l1;
            split_pair(x0, x1, h0, l0);
            split_pair(x2, x3, h1, l1);
            *reinterpret_cast<uint2*>(&Qh[r * H_ST + d]) = make_uint2(h0, h1);
            *reinterpret_cast<uint2*>(&Ql[r * H_ST + d]) = make_uint2(l0, l1);
        }
    }
    if (tid < FBQ) { m_sm[tid] = -1e30f; l_sm[tid] = 0.f; }

    float acc[8][4];
#pragma unroll
    for (int nt = 0; nt < 8; nt++)
#pragma unroll
        for (int q = 0; q < 4; q++) acc[nt][q] = 0.f;

    for (int kt = 0; kt <= qt; kt++) {
        __syncthreads();

        // ---- K (roped, rounded) rows; V rounded + TRANSPOSED into Vt ----
        {
            const size_t kvbase = ((size_t)(b * SEQ + kt * FBK)) * NKVCOLS + hk * HDIM;
#pragma unroll
            for (int it = 0; it < 8; it++) {
                const int f = tid + it * 256;
                const int r = f >> 5;
                const int d = (f & 31) * 4;
                const int t = kt * FBK + r;
                float4 kv = *reinterpret_cast<const float4*>(&Kf[kvbase + (size_t)r * NKVCOLS + d]);
                const float c0 = cosv[t * 64 + d / 2],     s0 = sinv[t * 64 + d / 2];
                const float c1 = cosv[t * 64 + d / 2 + 1], s1 = sinv[t * 64 + d / 2 + 1];
                float x0 = kv.x * c0 - kv.y * s0, x1 = kv.x * s0 + kv.y * c0;
                float x2 = kv.z * c1 - kv.w * s1, x3 = kv.z * s1 + kv.w * c1;
                *reinterpret_cast<uint2*>(&Kh[r * H_ST + d]) =
                    make_uint2(round_pair(x0, x1), round_pair(x2, x3));

                // V: row-scattered load (rv varies per lane), transposed store
                const int rv = tid & 63;
                const int dv = ((tid >> 6) + it * 4) * 4;
                float4 vv = *reinterpret_cast<const float4*>(&Vf[kvbase + (size_t)rv * NKVCOLS + dv]);
                Vt[(dv + 0) * VT_ST + rv] = __float2half_rn(vv.x);
                Vt[(dv + 1) * VT_ST + rv] = __float2half_rn(vv.y);
                Vt[(dv + 2) * VT_ST + rv] = __float2half_rn(vv.z);
                Vt[(dv + 3) * VT_ST + rv] = __float2half_rn(vv.w);
            }
        }
        __syncthreads();

        // ---- scores: S = (Qh+Ql) Kh^T (2-term, ldmatrix fragments) ----
        {
            float cs[4][4];
#pragma unroll
            for (int nt = 0; nt < 4; nt++)
#pragma unroll
                for (int q = 0; q < 4; q++) cs[nt][q] = 0.f;

#pragma unroll
            for (int ks = 0; ks < HDIM / 16; ks++) {
                const uint32_t kb = ks * 32;   // bytes
                uint32_t qh[4], ql[4];
                LDSM4(qh[0], qh[1], qh[2], qh[3], aQh + kb);
                LDSM4(ql[0], ql[1], ql[2], ql[3], aQl + kb);
#pragma unroll
                for (int p = 0; p < 2; p++) {
                    uint32_t k0, k1, k2, k3;
                    LDSM4(k0, k1, k2, k3, bK[p] + kb);
                    const uint32_t be[2] = {k0, k2}, bo[2] = {k1, k3};
                    mma_f16(cs[2 * p],     qh, be);
                    mma_f16(cs[2 * p],     ql, be);
                    mma_f16(cs[2 * p + 1], qh, bo);
                    mma_f16(cs[2 * p + 1], ql, bo);
                }
            }

            if (kt == qt) {
                const int grow0 = qt * FBQ + wmS + lr;
                const int gcolb = kt * FBK + wnS;
#pragma unroll
                for (int nt = 0; nt < 4; nt++) {
                    const int c = wnS + nt * 8 + lc * 2;
                    const int gc = gcolb + nt * 8 + lc * 2;
                    float v0 = (gc     > grow0) ? -1e30f : cs[nt][0] * SCALE;
                    float v1 = (gc + 1 > grow0) ? -1e30f : cs[nt][1] * SCALE;
                    float v2 = (gc     > grow0 + 8) ? -1e30f : cs[nt][2] * SCALE;
                    float v3 = (gc + 1 > grow0 + 8) ? -1e30f : cs[nt][3] * SCALE;
                    *reinterpret_cast<float2*>(&Ss[(wmS + lr) * SS_ST + c])     = make_float2(v0, v1);
                    *reinterpret_cast<float2*>(&Ss[(wmS + lr + 8) * SS_ST + c]) = make_float2(v2, v3);
                }
            } else {
#pragma unroll
                for (int nt = 0; nt < 4; nt++) {
                    const int c = wnS + nt * 8 + lc * 2;
                    *reinterpret_cast<float2*>(&Ss[(wmS + lr) * SS_ST + c]) =
                        make_float2(cs[nt][0] * SCALE, cs[nt][1] * SCALE);
                    *reinterpret_cast<float2*>(&Ss[(wmS + lr + 8) * SS_ST + c]) =
                        make_float2(cs[nt][2] * SCALE, cs[nt][3] * SCALE);
                }
            }
        }
        __syncthreads();

        // ---- online softmax ----
        {
            const int row = tid >> 2;
            const int g = tid & 3;
            float* Sr = &Ss[row * SS_ST + g * 16];
            float mloc = -1e30f;
#pragma unroll
            for (int jj = 0; jj < 16; jj++) mloc = fmaxf(mloc, Sr[jj]);
            mloc = fmaxf(mloc, __shfl_xor_sync(0xffffffffu, mloc, 1));
            mloc = fmaxf(mloc, __shfl_xor_sync(0xffffffffu, mloc, 2));
            const float mold = m_sm[row];
            const float mnew = fmaxf(mold, mloc);
            const float alpha = __expf(mold - mnew);
            float ssum = 0.f;
#pragma unroll
            for (int jj = 0; jj < 16; jj++) {
                float p = __expf(Sr[jj] - mnew);
                Sr[jj] = p;
                ssum += p;
            }
            ssum += __shfl_xor_sync(0xffffffffu, ssum, 1);
            ssum += __shfl_xor_sync(0xffffffffu, ssum, 2);
            if (g == 0) {
                m_sm[row] = mnew;
                l_sm[row] = l_sm[row] * alpha + ssum;
                a_sm[row] = alpha;
            }
        }
        __syncthreads();

        // ---- PV: O += Ph Vh (1-term; V fragments via ldmatrix on Vt) ----
        {
            const float al0 = a_sm[wmP + lr];
            const float al1 = a_sm[wmP + lr + 8];
#pragma unroll
            for (int nt = 0; nt < 8; nt++) {
                acc[nt][0] *= al0; acc[nt][1] *= al0;
                acc[nt][2] *= al1; acc[nt][3] *= al1;
            }

#pragma unroll
            for (int ks = 0; ks < FBK / 16; ks++) {
                const int kb = ks * 16 + 2 * lc;
                float2 p00 = *reinterpret_cast<const float2*>(&Ss[(wmP + lr) * SS_ST + kb]);
                float2 p01 = *reinterpret_cast<const float2*>(&Ss[(wmP + lr + 8) * SS_ST + kb]);
                float2 p10 = *reinterpret_cast<const float2*>(&Ss[(wmP + lr) * SS_ST + kb + 8]);
                float2 p11 = *reinterpret_cast<const float2*>(&Ss[(wmP + lr + 8) * SS_ST + kb + 8]);
                uint32_t ph[4];
                ph[0] = round_pair(p00.x, p00.y);
                ph[1] = round_pair(p01.x, p01.y);
                ph[2] = round_pair(p10.x, p10.y);
                ph[3] = round_pair(p11.x, p11.y);
                const uint32_t vkb = ks * 32;   // bytes into Vt k-dim
#pragma unroll
                for (int p = 0; p < 4; p++) {
                    uint32_t v0, v1, v2, v3;
                    LDSM4(v0, v1, v2, v3, bV[p] + vkb);
                    const uint32_t be[2] = {v0, v2}, bo[2] = {v1, v3};
                    mma_f16(acc[2 * p],     ph, be);
                    mma_f16(acc[2 * p + 1], ph, bo);
                }
            }
        }
    }

    __syncthreads();
    {
        const float inv0 = 1.0f / l_sm[wmP + lr];
        const float inv1 = 1.0f / l_sm[wmP + lr + 8];
        const size_t ob0 = ((size_t)(b * SEQ + qt * FBQ + wmP + lr)) * NQCOLS + h * HDIM;
        const size_t ob1 = ((size_t)(b * SEQ + qt * FBQ + wmP + lr + 8)) * NQCOLS + h * HDIM;
#pragma unroll
        for (int nt = 0; nt < 8; nt++) {
            const int c = wnP + nt * 8 + lc * 2;
            *reinterpret_cast<uint32_t*>(&Oh[ob0 + c]) =
                round_pair(acc[nt][0] * inv0, acc[nt][1] * inv0);
            *reinterpret_cast<uint32_t*>(&Oh[ob1 + c]) =
                round_pair(acc[nt][2] * inv1, acc[nt][3] * inv1);
        }
    }
}

// ---------------------------------------------------------------------------
// Launch
// ---------------------------------------------------------------------------
extern "C" void kernel_launch(void* const* d_in, const int* in_sizes, int n_in,
                              void* d_out, int out_size)
{
    (void)in_sizes; (void)n_in; (void)out_size;
    const float* X        = (const float*)d_in[0];
    const float* cosv     = (const float*)d_in[1];
    const float* sinv     = (const float*)d_in[2];
    // d_in[3] = position_ids (arange(S) broadcast; computed analytically)
    // d_in[4] = attention_mask (causal; applied analytically)
    const float* Wq       = (const float*)d_in[5];
    const float* Wk       = (const float*)d_in[6];
    const float* Wv       = (const float*)d_in[7];
    const float* Wo       = (const float*)d_in[8];
    float* out            = (float*)d_out;

    float *qp, *kp, *vp;
    __half *aoh, *xh, *wqkv, *woh;
    cudaGetSymbolAddress((void**)&qp,  g_Q);
    cudaGetSymbolAddress((void**)&kp,  g_K);
    cudaGetSymbolAddress((void**)&vp,  g_V);
    cudaGetSymbolAddress((void**)&aoh, g_AOh);
    cudaGetSymbolAddress((void**)&xh,  g_Xh);
    cudaGetSymbolAddress((void**)&wqkv, g_Wqkvh);
    cudaGetSymbolAddress((void**)&woh, g_Woh);

    // pre-convert operands (fused QKV weight buffer)
    {
        const int nX = MROWS * HID;
        const int nQ = NQCOLS * HID;
        const int nK = NKVCOLS * HID;
        cvt_round_kernel<<<nX / 4 / 256, 256>>>(X, xh, nX);
        cvt_round_kernel<<<nQ / 4 / 256, 256>>>(Wq, wqkv, nQ);
        cvt_round_kernel<<<nK / 4 / 256, 256>>>(Wk, wqkv + (size_t)NQCOLS * HID, nK);
        cvt_round_kernel<<<nK / 4 / 256, 256>>>(Wv, wqkv + (size_t)(NQCOLS + NKVCOLS) * HID, nK);
        cvt_round_kernel<<<nQ / 4 / 256, 256>>>(Wo, woh, nQ);
    }

    cudaFuncSetAttribute(hgemm_nt_1t, cudaFuncAttributeMaxDynamicSharedMemorySize,
                         GEMM_SMEM);

    // Fused QKV projection (one grid over 6144 output columns)
    hgemm_nt_1t<<<dim3(NQKV / TBN, MROWS / TBM), 256, GEMM_SMEM>>>(
        xh, wqkv, qp, kp, vp, HID);

    // Flash attention (RoPE fused; fp16 output; heavy tiles first)
    cudaFuncSetAttribute(flash_kernel, cudaFuncAttributeMaxDynamicSharedMemorySize,
                         FLASH_SMEM_BYTES);
    flash_kernel<<<dim3(SEQ / FBQ, BATCH * NHEADS), 256, FLASH_SMEM_BYTES>>>(
        qp, kp, vp, aoh, cosv, sinv);

    // Output projection -> d_out
    hgemm_nt_1t<<<dim3(NQCOLS / TBN, MROWS / TBM), 256, GEMM_SMEM>>>(
        aoh, woh, out, nullptr, nullptr, NQCOLS);
}

// round 16
// speedup vs baseline: 1.1178x; 1.1178x over previous
#include <cuda_runtime.h>
#include <cuda_fp16.h>
#include <math.h>
#include <stdint.h>

// Problem dims
constexpr int BATCH = 2;
constexpr int SEQ   = 2048;
constexpr int HID   = 4096;
constexpr int NHEADS = 32;
constexpr int NKVH   = 8;
constexpr int HDIM   = 128;
constexpr int GRP    = NHEADS / NKVH;          // 4
constexpr int MROWS  = BATCH * SEQ;            // 4096
constexpr int NQCOLS = NHEADS * HDIM;          // 4096
constexpr int NKVCOLS = NKVH * HDIM;           // 1024
constexpr int NQKV   = NQCOLS + 2 * NKVCOLS;   // 6144

// Scratch (device globals; no runtime allocation allowed)
__device__ float  g_Q [(size_t)MROWS * NQCOLS];
__device__ float  g_K [(size_t)MROWS * NKVCOLS];
__device__ float  g_V [(size_t)MROWS * NKVCOLS];
__device__ __half g_AOh[(size_t)MROWS * NQCOLS];
__device__ __half g_Xh [(size_t)MROWS * HID];
__device__ __half g_Wqkvh[(size_t)NQKV * HID];      // [Wq; Wk; Wv] rows
__device__ __half g_Woh[(size_t)HID * NQCOLS];

// ---------------------------------------------------------------------------
// helpers
// ---------------------------------------------------------------------------
__device__ __forceinline__ void mma_f16(float c[4], const uint32_t a[4], const uint32_t b[2]) {
    asm volatile(
        "mma.sync.aligned.m16n8k16.row.col.f32.f16.f16.f32 "
        "{%0,%1,%2,%3}, {%4,%5,%6,%7}, {%8,%9}, {%0,%1,%2,%3};\n"
        : "+f"(c[0]), "+f"(c[1]), "+f"(c[2]), "+f"(c[3])
        : "r"(a[0]), "r"(a[1]), "r"(a[2]), "r"(a[3]), "r"(b[0]), "r"(b[1]));
}

__device__ __forceinline__ void split_pair(float x0, float x1, uint32_t& hi, uint32_t& lo) {
    __half2 h = __float22half2_rn(make_float2(x0, x1));
    float l0 = x0 - __low2float(h);
    float l1 = x1 - __high2float(h);
    __half2 l = __float22half2_rn(make_float2(l0, l1));
    hi = *reinterpret_cast<uint32_t*>(&h);
    lo = *reinterpret_cast<uint32_t*>(&l);
}

__device__ __forceinline__ uint32_t round_pair(float x0, float x1) {
    __half2 h = __float22half2_rn(make_float2(x0, x1));
    return *reinterpret_cast<uint32_t*>(&h);
}

__device__ __forceinline__ uint32_t smem_u32(const void* p) {
    uint32_t a;
    asm("{ .reg .u64 t; cvta.to.shared.u64 t, %1; cvt.u32.u64 %0, t; }" : "=r"(a) : "l"(p));
    return a;
}

#define LDSM4(r0, r1, r2, r3, a) \
    asm volatile("ldmatrix.sync.aligned.m8n8.x4.shared.b16 {%0,%1,%2,%3}, [%4];" \
                 : "=r"(r0), "=r"(r1), "=r"(r2), "=r"(r3) : "r"(a))

#define LDSM4T(r0, r1, r2, r3, a) \
    asm volatile("ldmatrix.sync.aligned.m8n8.x4.trans.shared.b16 {%0,%1,%2,%3}, [%4];" \
                 : "=r"(r0), "=r"(r1), "=r"(r2), "=r"(r3) : "r"(a))

#define CP_ASYNC16(sa, gp) \
    asm volatile("cp.async.cg.shared.global [%0], [%1], 16;" :: "r"(sa), "l"(gp))
#define CP_COMMIT() asm volatile("cp.async.commit_group;" ::: "memory")
#define CP_WAIT(n)  asm volatile("cp.async.wait_group %0;" :: "n"(n) : "memory")

// ---------------------------------------------------------------------------
// pre-convert kernel (round fp32 -> fp16)
// ---------------------------------------------------------------------------
__global__ void cvt_round_kernel(const float* __restrict__ X, __half* __restrict__ Xh, int n)
{
    const int i = (blockIdx.x * 256 + threadIdx.x) * 4;
    if (i >= n) return;
    float4 v = *reinterpret_cast<const float4*>(X + i);
    *reinterpret_cast<uint2*>(Xh + i) =
        make_uint2(round_pair(v.x, v.y), round_pair(v.z, v.w));
}

// ---------------------------------------------------------------------------
// fp16 1-term GEMM NT, cp.async 2-stage pipeline, 3-way output routing.
// (R14-proven.)
// ---------------------------------------------------------------------------
constexpr int TBM = 128, TBN = 128, TBK = 32;
constexpr int GST = 40;
constexpr int TILE_HB  = TBM * GST;
constexpr int STAGE_B  = 2 * TILE_HB * 2;       // 20480
constexpr int GEMM_SMEM = 2 * STAGE_B;          // 40960

__global__ __launch_bounds__(256, 2)
void hgemm_nt_1t(const __half* __restrict__ A, const __half* __restrict__ Bh_g,
                 float* __restrict__ Cq, float* __restrict__ Ck, float* __restrict__ Cv,
                 int Kdim)
{
    extern __shared__ __half sm[];
    __half* Ahs = sm;
    __half* Bhs = sm + TILE_HB;

    const int tid  = threadIdx.x;
    const int lane = tid & 31;
    const int wid  = tid >> 5;
    const int wm   = (wid >> 1) * 32;
    const int wn   = (wid & 1) * 64;
    const int lr   = lane >> 2;
    const int lc   = lane & 3;
    const int bm0  = blockIdx.y * TBM;
    const int bn0  = blockIdx.x * TBN;

    const int crow = tid >> 2;
    const int ccol = (tid & 3) * 8;

    const __half* Ap  = A    + (size_t)(bm0 + crow) * Kdim + ccol;
    const __half* Bhp = Bh_g + (size_t)(bn0 + crow) * Kdim + ccol;
    const size_t rstep = (size_t)64 * Kdim;

    uint32_t aFill  = smem_u32(&Ahs[crow * GST + ccol]);
    uint32_t bhFill = smem_u32(&Bhs[crow * GST + ccol]);
    const uint32_t rowB = 64 * GST * 2;

    const int lrow = lane & 7;
    const int lblk = lane >> 3;
    const int rofs = (lblk & 1) * 8 + lrow;
    const int cofs = (lblk >> 1) * 8;
    uint32_t aAddr[2], bhAddr[4];
#pragma unroll
    for (int mt = 0; mt < 2; mt++)
        aAddr[mt] = smem_u32(&Ahs[(wm + mt * 16 + rofs) * GST + cofs]);
#pragma unroll
    for (int p = 0; p < 4; p++)
        bhAddr[p] = smem_u32(&Bhs[(wn + p * 16 + rofs) * GST + cofs]);

    auto fill = [&](int stage, int k0) {
        const uint32_t so = stage * (uint32_t)STAGE_B;
#pragma unroll
        for (int p = 0; p < 2; p++) {
            CP_ASYNC16(aFill  + so + p * rowB, Ap  + k0 + p * rstep);
            CP_ASYNC16(bhFill + so + p * rowB, Bhp + k0 + p * rstep);
        }
    };

    float cfr[2][8][4];
#pragma unroll
    for (int mt = 0; mt < 2; mt++)
#pragma unroll
        for (int nt = 0; nt < 8; nt++)
#pragma unroll
            for (int q = 0; q < 4; q++) cfr[mt][nt][q] = 0.f;

    const int nt_tiles = Kdim / TBK;

    fill(0, 0);
    CP_COMMIT();

    for (int i = 0; i < nt_tiles; i++) {
        if (i + 1 < nt_tiles) {
            fill((i + 1) & 1, (i + 1) * TBK);
            CP_COMMIT();
            CP_WAIT(1);
        } else {
            CP_WAIT(0);
        }
        __syncthreads();

        const uint32_t so = (i & 1) * (uint32_t)STAGE_B;
#pragma unroll
        for (int ks = 0; ks < 2; ks++) {
            const uint32_t kbyte = so + ks * 32;
            uint32_t ah[2][4];
            LDSM4(ah[0][0], ah[0][1], ah[0][2], ah[0][3], aAddr[0] + kbyte);
            LDSM4(ah[1][0], ah[1][1], ah[1][2], ah[1][3], aAddr[1] + kbyte);
#pragma unroll
            for (int p = 0; p < 4; p++) {
                uint32_t h0, h1, h2, h3;
                LDSM4(h0, h1, h2, h3, bhAddr[p] + kbyte);
                const uint32_t be[2] = {h0, h2}, bo[2] = {h1, h3};
                mma_f16(cfr[0][2 * p],     ah[0], be);
                mma_f16(cfr[1][2 * p],     ah[1], be);
                mma_f16(cfr[0][2 * p + 1], ah[0], bo);
                mma_f16(cfr[1][2 * p + 1], ah[1], bo);
            }
        }
        __syncthreads();
    }

    float* Cp;
    int Ndim, colbase;
    if (bn0 < NQCOLS)                 { Cp = Cq; Ndim = NQCOLS;  colbase = bn0; }
    else if (bn0 < NQCOLS + NKVCOLS)  { Cp = Ck; Ndim = NKVCOLS; colbase = bn0 - NQCOLS; }
    else                              { Cp = Cv; Ndim = NKVCOLS; colbase = bn0 - NQCOLS - NKVCOLS; }

#pragma unroll
    for (int mt = 0; mt < 2; mt++)
#pragma unroll
        for (int nt = 0; nt < 8; nt++) {
            const int row = bm0 + wm + mt * 16 + lr;
            const int col = colbase + wn + nt * 8 + lc * 2;
            *reinterpret_cast<float2*>(&Cp[(size_t)row * Ndim + col]) =
                make_float2(cfr[mt][nt][0], cfr[mt][nt][1]);
            *reinterpret_cast<float2*>(&Cp[(size_t)(row + 8) * Ndim + col]) =
                make_float2(cfr[mt][nt][2], cfr[mt][nt][3]);
        }
}

// ---------------------------------------------------------------------------
// Flash attention: scores = (Qh+Ql)·Kh (2-term), PV = Ph·Vh (1-term).
// Q/K/scores fragments via ldmatrix (row-major, GEMM recipe); V kept ROW-MAJOR
// in smem (coalesced uint2 fill, as R14) with PV B-fragments via
// ldmatrix.x4.TRANS (272B row stride => conflict-free phases).
// RoPE fused into Q/K loads. fp16 output. Heavy q-tiles first. 2 CTAs/SM.
// ---------------------------------------------------------------------------
constexpr int FBQ = 64;
constexpr int FBK = 64;
constexpr int H_ST  = 136;   // halves; 272B rows
constexpr int SS_ST = 68;
constexpr int FLASH_SMEM_BYTES =
    4 * (64 * H_ST * 2) + (FBQ * SS_ST + 3 * FBQ) * 4;   // 87808

__global__ __launch_bounds__(256, 2)
void flash_kernel(const float* __restrict__ Qf, const float* __restrict__ Kf,
                  const float* __restrict__ Vf, __half* __restrict__ Oh,
                  const float* __restrict__ cosv, const float* __restrict__ sinv)
{
    extern __shared__ char smraw[];
    __half* Qh = reinterpret_cast<__half*>(smraw);   // [64][136]
    __half* Ql = Qh + 64 * H_ST;                     // [64][136]
    __half* Kh = Ql + 64 * H_ST;                     // [64][136]
    __half* Vh = Kh + 64 * H_ST;                     // [64][136] row-major
    float*  Ss = reinterpret_cast<float*>(Vh + 64 * H_ST);
    float* m_sm = Ss + FBQ * SS_ST;
    float* l_sm = m_sm + FBQ;
    float* a_sm = l_sm + FBQ;

    const int tid = threadIdx.x;
    const int lane = tid & 31;
    const int wid = tid >> 5;
    const int lr = lane >> 2;
    const int lc = lane & 3;

    const int qt = gridDim.x - 1 - blockIdx.x;   // heavy tiles first
    const int bh = blockIdx.y;
    const int b = bh / NHEADS;
    const int h = bh - b * NHEADS;
    const int hk = h / GRP;

    const float SCALE = 0.0883883476483184f;

    const int wmS = (wid >> 1) * 16;
    const int wnS = (wid & 1) * 32;
    const int wmP = wmS;
    const int wnP = (wid & 1) * 64;

    // ldmatrix lane addressing (row-major recipe, as GEMM)
    const int lrow = lane & 7;
    const int lblk = lane >> 3;
    const int rofs = (lblk & 1) * 8 + lrow;
    const int cofs = (lblk >> 1) * 8;

    const uint32_t aQh = smem_u32(&Qh[(wmS + rofs) * H_ST + cofs]);
    const uint32_t aQl = smem_u32(&Ql[(wmS + rofs) * H_ST + cofs]);
    uint32_t bK[2];
#pragma unroll
    for (int p = 0; p < 2; p++)
        bK[p] = smem_u32(&Kh[(wnS + p * 16 + rofs) * H_ST + cofs]);

    // ldmatrix.trans lane addressing for V (rows = k, cols = n):
    // matrix j: j&1 -> k-half (0:k0-7, 1:k8-15); j>>1 -> n+8 offset.
    const int vrow = (lane & 7) + ((lane >> 3) & 1) * 8;
    const int vcol = (lane >> 4) * 8;
    uint32_t bV[4];
#pragma unroll
    for (int p = 0; p < 4; p++)
        bV[p] = smem_u32(&Vh[vrow * H_ST + wnP + p * 16 + vcol]);
    const uint32_t vkstep = 16 * H_ST * 2;   // bytes per k16 step

    // ---- Q tile: fused RoPE + hi/lo split ----
    {
        const size_t qbase = ((size_t)(b * SEQ + qt * FBQ)) * NQCOLS + h * HDIM;
#pragma unroll
        for (int it = 0; it < 8; it++) {
            const int f = tid + it * 256;
            const int r = f >> 5;
            const int d = (f & 31) * 4;
            const int t = qt * FBQ + r;
            float4 v = *reinterpret_cast<const float4*>(&Qf[qbase + (size_t)r * NQCOLS + d]);
            const float c0 = cosv[t * 64 + d / 2],     s0 = sinv[t * 64 + d / 2];
            const float c1 = cosv[t * 64 + d / 2 + 1], s1 = sinv[t * 64 + d / 2 + 1];
            float x0 = v.x * c0 - v.y * s0, x1 = v.x * s0 + v.y * c0;
            float x2 = v.z * c1 - v.w * s1, x3 = v.z * s1 + v.w * c1;
            uint32_t h0, l0, h1, l1;
            split_pair(x0, x1, h0, l0);
            split_pair(x2, x3, h1, l1);
            *reinterpret_cast<uint2*>(&Qh[r * H_ST + d]) = make_uint2(h0, h1);
            *reinterpret_cast<uint2*>(&Ql[r * H_ST + d]) = make_uint2(l0, l1);
        }
    }
    if (tid < FBQ) { m_sm[tid] = -1e30f; l_sm[tid] = 0.f; }

    float acc[8][4];
#pragma unroll
    for (int nt = 0; nt < 8; nt++)
#pragma unroll
        for (int q = 0; q < 4; q++) acc[nt][q] = 0.f;

    for (int kt = 0; kt <= qt; kt++) {
        __syncthreads();

        // ---- K (roped, rounded) and V (rounded) rows — coalesced, as R14 ----
        {
            const size_t kvbase = ((size_t)(b * SEQ + kt * FBK)) * NKVCOLS + hk * HDIM;
#pragma unroll
            for (int it = 0; it < 8; it++) {
                const int f = tid + it * 256;
                const int r = f >> 5;
                const int d = (f & 31) * 4;
                const int t = kt * FBK + r;
                float4 kv = *reinterpret_cast<const float4*>(&Kf[kvbase + (size_t)r * NKVCOLS + d]);
                const float c0 = cosv[t * 64 + d / 2],     s0 = sinv[t * 64 + d / 2];
                const float c1 = cosv[t * 64 + d / 2 + 1], s1 = sinv[t * 64 + d / 2 + 1];
                float x0 = kv.x * c0 - kv.y * s0, x1 = kv.x * s0 + kv.y * c0;
                float x2 = kv.z * c1 - kv.w * s1, x3 = kv.z * s1 + kv.w * c1;
                *reinterpret_cast<uint2*>(&Kh[r * H_ST + d]) =
                    make_uint2(round_pair(x0, x1), round_pair(x2, x3));
                float4 vv = *reinterpret_cast<const float4*>(&Vf[kvbase + (size_t)r * NKVCOLS + d]);
                *reinterpret_cast<uint2*>(&Vh[r * H_ST + d]) =
                    make_uint2(round_pair(vv.x, vv.y), round_pair(vv.z, vv.w));
            }
        }
        __syncthreads();

        // ---- scores: S = (Qh+Ql) Kh^T (2-term, ldmatrix fragments) ----
        {
            float cs[4][4];
#pragma unroll
            for (int nt = 0; nt < 4; nt++)
#pragma unroll
                for (int q = 0; q < 4; q++) cs[nt][q] = 0.f;

#pragma unroll
            for (int ks = 0; ks < HDIM / 16; ks++) {
                const uint32_t kb = ks * 32;   // bytes
                uint32_t qh[4], ql[4];
                LDSM4(qh[0], qh[1], qh[2], qh[3], aQh + kb);
                LDSM4(ql[0], ql[1], ql[2], ql[3], aQl + kb);
#pragma unroll
                for (int p = 0; p < 2; p++) {
                    uint32_t k0, k1, k2, k3;
                    LDSM4(k0, k1, k2, k3, bK[p] + kb);
                    const uint32_t be[2] = {k0, k2}, bo[2] = {k1, k3};
                    mma_f16(cs[2 * p],     qh, be);
                    mma_f16(cs[2 * p],     ql, be);
                    mma_f16(cs[2 * p + 1], qh, bo);
                    mma_f16(cs[2 * p + 1], ql, bo);
                }
            }

            if (kt == qt) {
                const int grow0 = qt * FBQ + wmS + lr;
                const int gcolb = kt * FBK + wnS;
#pragma unroll
                for (int nt = 0; nt < 4; nt++) {
                    const int c = wnS + nt * 8 + lc * 2;
                    const int gc = gcolb + nt * 8 + lc * 2;
                    float v0 = (gc     > grow0) ? -1e30f : cs[nt][0] * SCALE;
                    float v1 = (gc + 1 > grow0) ? -1e30f : cs[nt][1] * SCALE;
                    float v2 = (gc     > grow0 + 8) ? -1e30f : cs[nt][2] * SCALE;
                    float v3 = (gc + 1 > grow0 + 8) ? -1e30f : cs[nt][3] * SCALE;
                    *reinterpret_cast<float2*>(&Ss[(wmS + lr) * SS_ST + c])     = make_float2(v0, v1);
                    *reinterpret_cast<float2*>(&Ss[(wmS + lr + 8) * SS_ST + c]) = make_float2(v2, v3);
                }
            } else {
#pragma unroll
                for (int nt = 0; nt < 4; nt++) {
                    const int c = wnS + nt * 8 + lc * 2;
                    *reinterpret_cast<float2*>(&Ss[(wmS + lr) * SS_ST + c]) =
                        make_float2(cs[nt][0] * SCALE, cs[nt][1] * SCALE);
                    *reinterpret_cast<float2*>(&Ss[(wmS + lr + 8) * SS_ST + c]) =
                        make_float2(cs[nt][2] * SCALE, cs[nt][3] * SCALE);
                }
            }
        }
        __syncthreads();

        // ---- online softmax ----
        {
            const int row = tid >> 2;
            const int g = tid & 3;
            float* Sr = &Ss[row * SS_ST + g * 16];
            float mloc = -1e30f;
#pragma unroll
            for (int jj = 0; jj < 16; jj++) mloc = fmaxf(mloc, Sr[jj]);
            mloc = fmaxf(mloc, __shfl_xor_sync(0xffffffffu, mloc, 1));
            mloc = fmaxf(mloc, __shfl_xor_sync(0xffffffffu, mloc, 2));
            const float mold = m_sm[row];
            const float mnew = fmaxf(mold, mloc);
            const float alpha = __expf(mold - mnew);
            float ssum = 0.f;
#pragma unroll
            for (int jj = 0; jj < 16; jj++) {
                float p = __expf(Sr[jj] - mnew);
                Sr[jj] = p;
                ssum += p;
            }
            ssum += __shfl_xor_sync(0xffffffffu, ssum, 1);
            ssum += __shfl_xor_sync(0xffffffffu, ssum, 2);
            if (g == 0) {
                m_sm[row] = mnew;
                l_sm[row] = l_sm[row] * alpha + ssum;
                a_sm[row] = alpha;
            }
        }
        __syncthreads();

        // ---- PV: O += Ph Vh (1-term; B-fragments via ldmatrix.trans) ----
        {
            const float al0 = a_sm[wmP + lr];
            const float al1 = a_sm[wmP + lr + 8];
#pragma unroll
            for (int nt = 0; nt < 8; nt++) {
                acc[nt][0] *= al0; acc[nt][1] *= al0;
                acc[nt][2] *= al1; acc[nt][3] *= al1;
            }

#pragma unroll
            for (int ks = 0; ks < FBK / 16; ks++) {
                const int kb = ks * 16 + 2 * lc;
                float2 p00 = *reinterpret_cast<const float2*>(&Ss[(wmP + lr) * SS_ST + kb]);
                float2 p01 = *reinterpret_cast<const float2*>(&Ss[(wmP + lr + 8) * SS_ST + kb]);
                float2 p10 = *reinterpret_cast<const float2*>(&Ss[(wmP + lr) * SS_ST + kb + 8]);
                float2 p11 = *reinterpret_cast<const float2*>(&Ss[(wmP + lr + 8) * SS_ST + kb + 8]);
                uint32_t ph[4];
                ph[0] = round_pair(p00.x, p00.y);
                ph[1] = round_pair(p01.x, p01.y);
                ph[2] = round_pair(p10.x, p10.y);
                ph[3] = round_pair(p11.x, p11.y);
                const uint32_t vkb = ks * vkstep;
#pragma unroll
                for (int p = 0; p < 4; p++) {
                    uint32_t v0, v1, v2, v3;
                    LDSM4T(v0, v1, v2, v3, bV[p] + vkb);
                    const uint32_t be[2] = {v0, v1}, bo[2] = {v2, v3};
                    mma_f16(acc[2 * p],     ph, be);
                    mma_f16(acc[2 * p + 1], ph, bo);
                }
            }
        }
    }

    __syncthreads();
    {
        const float inv0 = 1.0f / l_sm[wmP + lr];
        const float inv1 = 1.0f / l_sm[wmP + lr + 8];
        const size_t ob0 = ((size_t)(b * SEQ + qt * FBQ + wmP + lr)) * NQCOLS + h * HDIM;
        const size_t ob1 = ((size_t)(b * SEQ + qt * FBQ + wmP + lr + 8)) * NQCOLS + h * HDIM;
#pragma unroll
        for (int nt = 0; nt < 8; nt++) {
            const int c = wnP + nt * 8 + lc * 2;
            *reinterpret_cast<uint32_t*>(&Oh[ob0 + c]) =
                round_pair(acc[nt][0] * inv0, acc[nt][1] * inv0);
            *reinterpret_cast<uint32_t*>(&Oh[ob1 + c]) =
                round_pair(acc[nt][2] * inv1, acc[nt][3] * inv1);
        }
    }
}

// ---------------------------------------------------------------------------
// Launch
// ---------------------------------------------------------------------------
extern "C" void kernel_launch(void* const* d_in, const int* in_sizes, int n_in,
                              void* d_out, int out_size)
{
    (void)in_sizes; (void)n_in; (void)out_size;
    const float* X        = (const float*)d_in[0];
    const float* cosv     = (const float*)d_in[1];
    const float* sinv     = (const float*)d_in[2];
    // d_in[3] = position_ids (arange(S) broadcast; computed analytically)
    // d_in[4] = attention_mask (causal; applied analytically)
    const float* Wq       = (const float*)d_in[5];
    const float* Wk       = (const float*)d_in[6];
    const float* Wv       = (const float*)d_in[7];
    const float* Wo       = (const float*)d_in[8];
    float* out            = (float*)d_out;

    float *qp, *kp, *vp;
    __half *aoh, *xh, *wqkv, *woh;
    cudaGetSymbolAddress((void**)&qp,  g_Q);
    cudaGetSymbolAddress((void**)&kp,  g_K);
    cudaGetSymbolAddress((void**)&vp,  g_V);
    cudaGetSymbolAddress((void**)&aoh, g_AOh);
    cudaGetSymbolAddress((void**)&xh,  g_Xh);
    cudaGetSymbolAddress((void**)&wqkv, g_Wqkvh);
    cudaGetSymbolAddress((void**)&woh, g_Woh);

    // pre-convert operands (fused QKV weight buffer)
    {
        const int nX = MROWS * HID;
        const int nQ = NQCOLS * HID;
        const int nK = NKVCOLS * HID;
        cvt_round_kernel<<<nX / 4 / 256, 256>>>(X, xh, nX);
        cvt_round_kernel<<<nQ / 4 / 256, 256>>>(Wq, wqkv, nQ);
        cvt_round_kernel<<<nK / 4 / 256, 256>>>(Wk, wqkv + (size_t)NQCOLS * HID, nK);
        cvt_round_kernel<<<nK / 4 / 256, 256>>>(Wv, wqkv + (size_t)(NQCOLS + NKVCOLS) * HID, nK);
        cvt_round_kernel<<<nQ / 4 / 256, 256>>>(Wo, woh, nQ);
    }

    cudaFuncSetAttribute(hgemm_nt_1t, cudaFuncAttributeMaxDynamicSharedMemorySize,
                         GEMM_SMEM);

    // Fused QKV projection (one grid over 6144 output columns)
    hgemm_nt_1t<<<dim3(NQKV / TBN, MROWS / TBM), 256, GEMM_SMEM>>>(
        xh, wqkv, qp, kp, vp, HID);

    // Flash attention (RoPE fused; fp16 output; heavy tiles first)
    cudaFuncSetAttribute(flash_kernel, cudaFuncAttributeMaxDynamicSharedMemorySize,
                         FLASH_SMEM_BYTES);
    flash_kernel<<<dim3(SEQ / FBQ, BATCH * NHEADS), 256, FLASH_SMEM_BYTES>>>(
        qp, kp, vp, aoh, cosv, sinv);

    // Output projection -> d_out
    hgemm_nt_1t<<<dim3(NQCOLS / TBN, MROWS / TBM), 256, GEMM_SMEM>>>(
        aoh, woh, out, nullptr, nullptr, NQCOLS);
}